// round 11
// baseline (speedup 1.0000x reference)
#include <cuda_runtime.h>
#include <math.h>
#include <stdint.h>

#define T_DIM 512
#define B_DIM 64
#define I_DIM 1024
#define H_DIM 2048
#define TB (T_DIM * B_DIM)
#define NB 148          // persistent grid: one block per SM
#define NT 512          // 16 warps: 4 K-streams x 128 threads
#define KCH 32
#define HS_ST 68        // float stride of Hs rows ([k][m])
#define WS_ST 34        // u64 stride of Ws rows ([k][n])
// per-stream: Hs 2*32*68*4 = 17408 B ; Ws 2*32*34*8 = 17408 B
#define HS_BYTES 17408
#define STREAM_BYTES (17408 + 17408)
#define SMEM_BYTES (4 * STREAM_BYTES)   // 139264

typedef unsigned long long u64;

// ---- static device scratch (no allocations allowed) ----
__device__ float g_XZ[(size_t)TB * H_DIM];
__device__ float g_XR[(size_t)TB * H_DIM];
__device__ float g_XH[(size_t)TB * H_DIM];
__device__ float g_H[2][B_DIM * H_DIM];
__device__ float g_Z[B_DIM * H_DIM];
__device__ float g_RH[B_DIM * H_DIM];
__device__ unsigned g_bar_cnt;           // reset via memset each launch

__device__ __forceinline__ u64 dup_f32(float f) {
    unsigned u = __float_as_uint(f);
    return (u64)u | ((u64)u << 32);
}
__device__ __forceinline__ void fma2(u64& d, u64 a, u64 b) {
    asm("fma.rn.f32x2 %0, %1, %2, %0;" : "+l"(d) : "l"(a), "l"(b));
}
__device__ __forceinline__ void add2(u64& d, u64 a) {
    asm("add.rn.f32x2 %0, %0, %1;" : "+l"(d) : "l"(a));
}
__device__ __forceinline__ float2 unpack2(u64 v) {
    float2 r;
    r.x = __uint_as_float((unsigned)v);
    r.y = __uint_as_float((unsigned)(v >> 32));
    return r;
}

// ============================================================
// 64(M) x 32(N) x K fp32 GEMM, 512 threads as 4 K-streams x 128.
// A: M-major (64 x K). W: K-major (K x N), cols [n0, n0+32).
// Stream s handles K range [s*K/4, (s+1)*K/4), double-buffered
// 32-k chunks in its own smem region. Final cross-stream f32x2
// reduction leaves the result in stream 0's acc[2][4]:
//   thread (ty=r>>3, tx=r&7) of stream 0 owns rows ty*4+{0..3}
//   (2 f32x2 row-pairs) x cols n0+tx*4+{0..3}.
// ============================================================
__device__ __forceinline__ void gemm4s(const float* __restrict__ A,
                                       const float* __restrict__ W,
                                       int K, int N, int n0, int tid,
                                       char* sraw, u64 acc[2][4])
{
    const int s  = tid >> 7;
    const int r  = tid & 127;
    float* Hs = (float*)(sraw + s * STREAM_BYTES);
    u64*   Ws = (u64*)(sraw + s * STREAM_BYTES + HS_BYTES);
    const int tx = r & 7;
    const int ty = r >> 3;
    const int Ks = K >> 2;
    const int koff = s * Ks;

    // fill roles
    const int h_row0 = r >> 3;          // +q*16 per task (q=0..3)
    const int h_kq   = (r & 7) * 4;
    const int w_k0   = r >> 3;          // +q*16 per task (q=0..1)
    const int w_nq   = (r & 7) * 4;

#pragma unroll
    for (int i = 0; i < 2; i++)
#pragma unroll
        for (int j = 0; j < 4; j++) acc[i][j] = 0ull;

    float4 ha[4], wa[2];

    // ---- prologue: load + store chunk 0 ----
#pragma unroll
    for (int q = 0; q < 4; q++)
        ha[q] = *(const float4*)&A[(size_t)(h_row0 + q * 16) * K + koff + h_kq];
#pragma unroll
    for (int q = 0; q < 2; q++)
        wa[q] = *(const float4*)&W[(size_t)(koff + w_k0 + q * 16) * N + n0 + w_nq];
#pragma unroll
    for (int q = 0; q < 4; q++) {
        float* p = &Hs[(size_t)h_kq * HS_ST + h_row0 + q * 16];
        p[0 * HS_ST] = ha[q].x; p[1 * HS_ST] = ha[q].y;
        p[2 * HS_ST] = ha[q].z; p[3 * HS_ST] = ha[q].w;
    }
#pragma unroll
    for (int q = 0; q < 2; q++) {
        u64* p = &Ws[(size_t)(w_k0 + q * 16) * WS_ST + w_nq];
        p[0] = dup_f32(wa[q].x); p[1] = dup_f32(wa[q].y);
        p[2] = dup_f32(wa[q].z); p[3] = dup_f32(wa[q].w);
    }
    __syncthreads();

    const int NIT = Ks / KCH;
    int buf = 0;
#pragma unroll 1
    for (int it = 0; it < NIT - 1; ++it) {
        const int kn = koff + (it + 1) * KCH;
        // prefetch next chunk into registers
#pragma unroll
        for (int q = 0; q < 4; q++)
            ha[q] = *(const float4*)&A[(size_t)(h_row0 + q * 16) * K + kn + h_kq];
#pragma unroll
        for (int q = 0; q < 2; q++)
            wa[q] = *(const float4*)&W[(size_t)(kn + w_k0 + q * 16) * N + n0 + w_nq];

        // compute current chunk
        const float* hb = &Hs[(size_t)buf * KCH * HS_ST];
        const u64*   wb = &Ws[(size_t)buf * KCH * WS_ST];
#pragma unroll
        for (int k = 0; k < KCH; ++k) {
            ulonglong2 av = *(const ulonglong2*)&hb[k * HS_ST + ty * 4];
            ulonglong2 b0 = *(const ulonglong2*)&wb[k * WS_ST + tx * 4];
            ulonglong2 b1 = *(const ulonglong2*)&wb[k * WS_ST + tx * 4 + 2];
            fma2(acc[0][0], av.x, b0.x); fma2(acc[0][1], av.x, b0.y);
            fma2(acc[0][2], av.x, b1.x); fma2(acc[0][3], av.x, b1.y);
            fma2(acc[1][0], av.y, b0.x); fma2(acc[1][1], av.y, b0.y);
            fma2(acc[1][2], av.y, b1.x); fma2(acc[1][3], av.y, b1.y);
        }

        // stage next chunk
        const int nb = buf ^ 1;
#pragma unroll
        for (int q = 0; q < 4; q++) {
            float* p = &Hs[(size_t)(nb * KCH + h_kq) * HS_ST + h_row0 + q * 16];
            p[0 * HS_ST] = ha[q].x; p[1 * HS_ST] = ha[q].y;
            p[2 * HS_ST] = ha[q].z; p[3 * HS_ST] = ha[q].w;
        }
#pragma unroll
        for (int q = 0; q < 2; q++) {
            u64* p = &Ws[(size_t)(nb * KCH + w_k0 + q * 16) * WS_ST + w_nq];
            p[0] = dup_f32(wa[q].x); p[1] = dup_f32(wa[q].y);
            p[2] = dup_f32(wa[q].z); p[3] = dup_f32(wa[q].w);
        }
        __syncthreads();
        buf = nb;
    }
    // final chunk compute
    {
        const float* hb = &Hs[(size_t)buf * KCH * HS_ST];
        const u64*   wb = &Ws[(size_t)buf * KCH * WS_ST];
#pragma unroll
        for (int k = 0; k < KCH; ++k) {
            ulonglong2 av = *(const ulonglong2*)&hb[k * HS_ST + ty * 4];
            ulonglong2 b0 = *(const ulonglong2*)&wb[k * WS_ST + tx * 4];
            ulonglong2 b1 = *(const ulonglong2*)&wb[k * WS_ST + tx * 4 + 2];
            fma2(acc[0][0], av.x, b0.x); fma2(acc[0][1], av.x, b0.y);
            fma2(acc[0][2], av.x, b1.x); fma2(acc[0][3], av.x, b1.y);
            fma2(acc[1][0], av.y, b0.x); fma2(acc[1][1], av.y, b0.y);
            fma2(acc[1][2], av.y, b1.x); fma2(acc[1][3], av.y, b1.y);
        }
    }
    __syncthreads();

    // ---- cross-stream reduction into stream 0 ----
    u64* red = (u64*)sraw;                 // reuse stream-0 tile space (24 KB)
    if (s > 0) {
        u64* dst = red + (size_t)(s - 1) * 128 * 8 + r * 8;
#pragma unroll
        for (int i = 0; i < 2; i++)
#pragma unroll
            for (int j = 0; j < 4; j++) dst[i * 4 + j] = acc[i][j];
    }
    __syncthreads();
    if (s == 0) {
#pragma unroll
        for (int ss = 0; ss < 3; ss++) {
            const u64* src = red + (size_t)ss * 128 * 8 + r * 8;
#pragma unroll
            for (int i = 0; i < 2; i++)
#pragma unroll
                for (int j = 0; j < 4; j++) add2(acc[i][j], src[i * 4 + j]);
        }
    }
    // NOTE: caller always has a block-wide barrier (grid_sync) before the
    // next gemm4s call, which protects the red region from prologue writes.
}

// ============================================================
// Precompute: g_X?[(t*B+b)][j] = X[t,b,:] @ W_x?[:,j] + b_?[j]
// grid = (H_DIM/32, TB/64, 3). Bias added HERE ONLY.
// ============================================================
__global__ void __launch_bounds__(NT, 1)
xproj_kernel(const float* __restrict__ X,
             const float* __restrict__ Wz,
             const float* __restrict__ Wr,
             const float* __restrict__ Wh,
             const float* __restrict__ bz,
             const float* __restrict__ br,
             const float* __restrict__ bh)
{
    extern __shared__ char sraw[];
    const float* W;
    const float* bias;
    float* out;
    int g = blockIdx.z;
    if (g == 0)      { W = Wz; bias = bz; out = g_XZ; }
    else if (g == 1) { W = Wr; bias = br; out = g_XR; }
    else             { W = Wh; bias = bh; out = g_XH; }

    const int n0 = blockIdx.x * 32;
    const int m0 = blockIdx.y * 64;
    const int tid = threadIdx.x;

    u64 acc[2][4];
    gemm4s(X + (size_t)m0 * I_DIM, W, I_DIM, H_DIM, n0, tid, sraw, acc);

    if ((tid >> 7) == 0) {
        const int r = tid & 127;
        const int tx = r & 7;
        const int ty = r >> 3;
#pragma unroll
        for (int rp = 0; rp < 2; ++rp)
#pragma unroll
            for (int cc = 0; cc < 4; ++cc) {
                float2 v = unpack2(acc[rp][cc]);
                int mrow = m0 + ty * 4 + rp * 2;
                int c = n0 + tx * 4 + cc;
                float bb = bias[c];
                out[(size_t)mrow * H_DIM + c] = v.x + bb;
                out[(size_t)(mrow + 1) * H_DIM + c] = v.y + bb;
            }
    }
}

// ============================================================
// Grid-wide barrier (monotonic counter; host resets per launch).
// ============================================================
__device__ __forceinline__ void grid_sync(unsigned target)
{
    __syncthreads();
    if (threadIdx.x == 0) {
        __threadfence();
        atomicAdd(&g_bar_cnt, 1u);
        unsigned v;
        for (;;) {
            asm volatile("ld.global.acquire.gpu.u32 %0, [%1];"
                         : "=r"(v) : "l"(&g_bar_cnt));
            if (v >= target) break;
            __nanosleep(64);
        }
    }
    __syncthreads();
}

// ============================================================
// Persistent recurrence. Per step:
//  P1 (blk 0..127): Z = sig(XZ + H@Whz); RH = sig(XR + H@Whr) * H
//  barrier
//  P2 (blk 0..63):  Hnew = Z*H + (1-Z)*tanh(XH + RH@Whh)
//     (blk 64..95): Y[t-1] = H@Whq + b_hq
//  barrier
// ============================================================
__global__ void __launch_bounds__(NT, 1)
gru_persistent(const float* __restrict__ Whz,
               const float* __restrict__ Whr,
               const float* __restrict__ Whh,
               const float* __restrict__ Whq,
               const float* __restrict__ bq,
               float* __restrict__ out,
               int write_hfinal)
{
    extern __shared__ char sraw[];
    const int blk = blockIdx.x;
    const int tid = threadIdx.x;
    const int r = tid & 127;
    const int tx = r & 7;
    const int ty = r >> 3;
    const bool epi = (tid >> 7) == 0;
    unsigned epoch = 0;
    u64 acc[2][4];

    for (int t = 0; t < T_DIM; ++t) {
        const float* Hold = g_H[t & 1];
        float* Hnew = g_H[(t + 1) & 1];

        // ---------------- P1: gates Z, R ----------------
        if (blk < 128) {
            const int gate = blk >> 6;
            const int n0 = (blk & 63) * 32;
            const float* W  = gate ? Whr  : Whz;
            const float* Xp = gate ? g_XR : g_XZ;

            gemm4s(Hold, W, H_DIM, H_DIM, n0, tid, sraw, acc);

            if (epi) {
#pragma unroll
                for (int rp = 0; rp < 2; ++rp)
#pragma unroll
                    for (int cc = 0; cc < 4; ++cc) {
                        float2 v = unpack2(acc[rp][cc]);
                        int b = ty * 4 + rp * 2;
                        int c = n0 + tx * 4 + cc;
#pragma unroll
                        for (int rr = 0; rr < 2; ++rr) {
                            float vv = rr ? v.y : v.x;
                            float x = Xp[(size_t)(t * B_DIM + b + rr) * H_DIM + c] + vv;
                            float sg = 1.0f / (1.0f + expf(-x));
                            if (gate) g_RH[(b + rr) * H_DIM + c] = sg * Hold[(b + rr) * H_DIM + c];
                            else      g_Z[(b + rr) * H_DIM + c]  = sg;
                        }
                    }
            }
        }
        epoch++; grid_sync(epoch * NB);

        // ---------------- P2: Hnew and Y[t-1] ----------------
        if (blk < 64) {
            const int n0 = blk * 32;
            gemm4s(g_RH, Whh, H_DIM, H_DIM, n0, tid, sraw, acc);

            if (epi) {
#pragma unroll
                for (int rp = 0; rp < 2; ++rp)
#pragma unroll
                    for (int cc = 0; cc < 4; ++cc) {
                        float2 v = unpack2(acc[rp][cc]);
                        int b = ty * 4 + rp * 2;
                        int c = n0 + tx * 4 + cc;
#pragma unroll
                        for (int rr = 0; rr < 2; ++rr) {
                            float vv = rr ? v.y : v.x;
                            float ht = tanhf(g_XH[(size_t)(t * B_DIM + b + rr) * H_DIM + c] + vv);
                            float z = g_Z[(b + rr) * H_DIM + c];
                            Hnew[(b + rr) * H_DIM + c] =
                                z * Hold[(b + rr) * H_DIM + c] + (1.0f - z) * ht;
                        }
                    }
            }
        } else if (blk < 96 && t > 0) {
            const int n0 = (blk - 64) * 32;
            gemm4s(Hold, Whq, H_DIM, I_DIM, n0, tid, sraw, acc);

            if (epi) {
#pragma unroll
                for (int rp = 0; rp < 2; ++rp)
#pragma unroll
                    for (int cc = 0; cc < 4; ++cc) {
                        float2 v = unpack2(acc[rp][cc]);
                        int b = ty * 4 + rp * 2;
                        int c = n0 + tx * 4 + cc;
                        float bb = bq[c];
                        out[(size_t)((t - 1) * B_DIM + b) * I_DIM + c] = v.x + bb;
                        out[(size_t)((t - 1) * B_DIM + b + 1) * I_DIM + c] = v.y + bb;
                    }
            }
        }
        epoch++; grid_sync(epoch * NB);
    }

    // ---------------- tail: Y[T-1] + optional H_final ----------------
    const float* Hfin = g_H[T_DIM & 1];   // T even -> g_H[0]
    if (blk < 32) {
        const int n0 = blk * 32;
        gemm4s(Hfin, Whq, H_DIM, I_DIM, n0, tid, sraw, acc);
        if (epi) {
#pragma unroll
            for (int rp = 0; rp < 2; ++rp)
#pragma unroll
                for (int cc = 0; cc < 4; ++cc) {
                    float2 v = unpack2(acc[rp][cc]);
                    int b = ty * 4 + rp * 2;
                    int c = n0 + tx * 4 + cc;
                    float bb = bq[c];
                    out[(size_t)((T_DIM - 1) * B_DIM + b) * I_DIM + c] = v.x + bb;
                    out[(size_t)((T_DIM - 1) * B_DIM + b + 1) * I_DIM + c] = v.y + bb;
                }
        }
    } else if (blk >= 32 && blk < 64 && write_hfinal) {
        float* dst = out + (size_t)TB * I_DIM;
        int base = ((blk - 32) * NT + tid) * 8;   // 32*512*8 = 131072
        *(float4*)&dst[base]     = *(const float4*)&Hfin[base];
        *(float4*)&dst[base + 4] = *(const float4*)&Hfin[base + 4];
    }
}

extern "C" void kernel_launch(void* const* d_in, const int* in_sizes, int n_in,
                              void* d_out, int out_size)
{
    (void)in_sizes; (void)n_in;
    const float* inputs = (const float*)d_in[0];
    const float* state  = (const float*)d_in[1];
    const float* W_xz   = (const float*)d_in[2];
    const float* W_hz   = (const float*)d_in[3];
    const float* b_z    = (const float*)d_in[4];
    const float* W_xr   = (const float*)d_in[5];
    const float* W_hr   = (const float*)d_in[6];
    const float* b_r    = (const float*)d_in[7];
    const float* W_xh   = (const float*)d_in[8];
    const float* W_hh   = (const float*)d_in[9];
    const float* b_h    = (const float*)d_in[10];
    const float* W_hq   = (const float*)d_in[11];
    const float* b_hq   = (const float*)d_in[12];
    float* out = (float*)d_out;

    static int attrs_set = 0;
    if (!attrs_set) {
        cudaFuncSetAttribute(xproj_kernel,
                             cudaFuncAttributeMaxDynamicSharedMemorySize, SMEM_BYTES);
        cudaFuncSetAttribute(gru_persistent,
                             cudaFuncAttributeMaxDynamicSharedMemorySize, SMEM_BYTES);
        attrs_set = 1;
    }

    float* hbuf = nullptr;
    cudaGetSymbolAddress((void**)&hbuf, g_H);
    unsigned* barp = nullptr;
    cudaGetSymbolAddress((void**)&barp, g_bar_cnt);

    cudaMemsetAsync(barp, 0, sizeof(unsigned), 0);
    cudaMemcpyAsync(hbuf, state, (size_t)B_DIM * H_DIM * sizeof(float),
                    cudaMemcpyDeviceToDevice, 0);

    dim3 gx(H_DIM / 32, TB / 64, 3);
    xproj_kernel<<<gx, NT, SMEM_BYTES>>>(inputs, W_xz, W_xr, W_xh, b_z, b_r, b_h);

    long long need = (long long)TB * I_DIM + (long long)B_DIM * H_DIM;
    int write_hfinal = ((long long)out_size >= need) ? 1 : 0;

    gru_persistent<<<NB, NT, SMEM_BYTES>>>(W_hz, W_hr, W_hh, W_hq, b_hq, out, write_hfinal);
}

// round 15
// speedup vs baseline: 1.0003x; 1.0003x over previous
#include <cuda_runtime.h>
#include <math.h>
#include <stdint.h>

#define T_DIM 512
#define B_DIM 64
#define I_DIM 1024
#define H_DIM 2048
#define TB (T_DIM * B_DIM)
#define NB 148          // persistent grid: one block per SM
#define NT 512          // 16 warps: 4 K-streams x 128 threads
#define KCH 32
#define HS_ST 68        // float stride of Hs rows ([k][m])
#define WS_ST 34        // u64 stride of Ws rows ([k][n])
// per-stream: Hs 2*32*68*4 = 17408 B ; Ws 2*32*34*8 = 17408 B
#define HS_BYTES 17408
#define STREAM_BYTES (17408 + 17408)
#define SMEM_BYTES (4 * STREAM_BYTES)   // 139264

typedef unsigned long long u64;

// ---- static device scratch (no allocations allowed) ----
__device__ float g_XZ[(size_t)TB * H_DIM];
__device__ float g_XR[(size_t)TB * H_DIM];
__device__ float g_XH[(size_t)TB * H_DIM];
__device__ float g_H[2][B_DIM * H_DIM];
__device__ float g_Z[B_DIM * H_DIM];
__device__ float g_RH[B_DIM * H_DIM];
__device__ unsigned g_bar_cnt;           // reset via memset each launch

__device__ __forceinline__ u64 dup_f32(float f) {
    unsigned u = __float_as_uint(f);
    return (u64)u | ((u64)u << 32);
}
__device__ __forceinline__ void fma2(u64& d, u64 a, u64 b) {
    asm("fma.rn.f32x2 %0, %1, %2, %0;" : "+l"(d) : "l"(a), "l"(b));
}
__device__ __forceinline__ void add2(u64& d, u64 a) {
    asm("add.rn.f32x2 %0, %0, %1;" : "+l"(d) : "l"(a));
}
__device__ __forceinline__ float2 unpack2(u64 v) {
    float2 r;
    r.x = __uint_as_float((unsigned)v);
    r.y = __uint_as_float((unsigned)(v >> 32));
    return r;
}

// ============================================================
// 64(M) x 32(N) x K fp32 GEMM, 512 threads as 4 K-streams x 128.
// A: M-major (64 x K). W: K-major (K x N), cols [n0, n0+32).
// Stream s handles K range [s*K/4, (s+1)*K/4), double-buffered
// 32-k chunks in its own smem region. Final cross-stream f32x2
// reduction leaves the result in stream 0's acc[2][4]:
//   thread (ty=r>>3, tx=r&7) of stream 0 owns rows ty*4+{0..3}
//   (2 f32x2 row-pairs) x cols n0+tx*4+{0..3}.
// ============================================================
__device__ __forceinline__ void gemm4s(const float* __restrict__ A,
                                       const float* __restrict__ W,
                                       int K, int N, int n0, int tid,
                                       char* sraw, u64 acc[2][4])
{
    const int s  = tid >> 7;
    const int r  = tid & 127;
    float* Hs = (float*)(sraw + s * STREAM_BYTES);
    u64*   Ws = (u64*)(sraw + s * STREAM_BYTES + HS_BYTES);
    const int tx = r & 7;
    const int ty = r >> 3;
    const int Ks = K >> 2;
    const int koff = s * Ks;

    // fill roles
    const int h_row0 = r >> 3;          // +q*16 per task (q=0..3)
    const int h_kq   = (r & 7) * 4;
    const int w_k0   = r >> 3;          // +q*16 per task (q=0..1)
    const int w_nq   = (r & 7) * 4;

#pragma unroll
    for (int i = 0; i < 2; i++)
#pragma unroll
        for (int j = 0; j < 4; j++) acc[i][j] = 0ull;

    float4 ha[4], wa[2];

    // ---- prologue: load + store chunk 0 ----
#pragma unroll
    for (int q = 0; q < 4; q++)
        ha[q] = *(const float4*)&A[(size_t)(h_row0 + q * 16) * K + koff + h_kq];
#pragma unroll
    for (int q = 0; q < 2; q++)
        wa[q] = *(const float4*)&W[(size_t)(koff + w_k0 + q * 16) * N + n0 + w_nq];
#pragma unroll
    for (int q = 0; q < 4; q++) {
        float* p = &Hs[(size_t)h_kq * HS_ST + h_row0 + q * 16];
        p[0 * HS_ST] = ha[q].x; p[1 * HS_ST] = ha[q].y;
        p[2 * HS_ST] = ha[q].z; p[3 * HS_ST] = ha[q].w;
    }
#pragma unroll
    for (int q = 0; q < 2; q++) {
        u64* p = &Ws[(size_t)(w_k0 + q * 16) * WS_ST + w_nq];
        p[0] = dup_f32(wa[q].x); p[1] = dup_f32(wa[q].y);
        p[2] = dup_f32(wa[q].z); p[3] = dup_f32(wa[q].w);
    }
    __syncthreads();

    const int NIT = Ks / KCH;
    int buf = 0;
#pragma unroll 1
    for (int it = 0; it < NIT - 1; ++it) {
        const int kn = koff + (it + 1) * KCH;
        // prefetch next chunk into registers
#pragma unroll
        for (int q = 0; q < 4; q++)
            ha[q] = *(const float4*)&A[(size_t)(h_row0 + q * 16) * K + kn + h_kq];
#pragma unroll
        for (int q = 0; q < 2; q++)
            wa[q] = *(const float4*)&W[(size_t)(kn + w_k0 + q * 16) * N + n0 + w_nq];

        // compute current chunk
        const float* hb = &Hs[(size_t)buf * KCH * HS_ST];
        const u64*   wb = &Ws[(size_t)buf * KCH * WS_ST];
#pragma unroll
        for (int k = 0; k < KCH; ++k) {
            ulonglong2 av = *(const ulonglong2*)&hb[k * HS_ST + ty * 4];
            ulonglong2 b0 = *(const ulonglong2*)&wb[k * WS_ST + tx * 4];
            ulonglong2 b1 = *(const ulonglong2*)&wb[k * WS_ST + tx * 4 + 2];
            fma2(acc[0][0], av.x, b0.x); fma2(acc[0][1], av.x, b0.y);
            fma2(acc[0][2], av.x, b1.x); fma2(acc[0][3], av.x, b1.y);
            fma2(acc[1][0], av.y, b0.x); fma2(acc[1][1], av.y, b0.y);
            fma2(acc[1][2], av.y, b1.x); fma2(acc[1][3], av.y, b1.y);
        }

        // stage next chunk
        const int nb = buf ^ 1;
#pragma unroll
        for (int q = 0; q < 4; q++) {
            float* p = &Hs[(size_t)(nb * KCH + h_kq) * HS_ST + h_row0 + q * 16];
            p[0 * HS_ST] = ha[q].x; p[1 * HS_ST] = ha[q].y;
            p[2 * HS_ST] = ha[q].z; p[3 * HS_ST] = ha[q].w;
        }
#pragma unroll
        for (int q = 0; q < 2; q++) {
            u64* p = &Ws[(size_t)(nb * KCH + w_k0 + q * 16) * WS_ST + w_nq];
            p[0] = dup_f32(wa[q].x); p[1] = dup_f32(wa[q].y);
            p[2] = dup_f32(wa[q].z); p[3] = dup_f32(wa[q].w);
        }
        __syncthreads();
        buf = nb;
    }
    // final chunk compute
    {
        const float* hb = &Hs[(size_t)buf * KCH * HS_ST];
        const u64*   wb = &Ws[(size_t)buf * KCH * WS_ST];
#pragma unroll
        for (int k = 0; k < KCH; ++k) {
            ulonglong2 av = *(const ulonglong2*)&hb[k * HS_ST + ty * 4];
            ulonglong2 b0 = *(const ulonglong2*)&wb[k * WS_ST + tx * 4];
            ulonglong2 b1 = *(const ulonglong2*)&wb[k * WS_ST + tx * 4 + 2];
            fma2(acc[0][0], av.x, b0.x); fma2(acc[0][1], av.x, b0.y);
            fma2(acc[0][2], av.x, b1.x); fma2(acc[0][3], av.x, b1.y);
            fma2(acc[1][0], av.y, b0.x); fma2(acc[1][1], av.y, b0.y);
            fma2(acc[1][2], av.y, b1.x); fma2(acc[1][3], av.y, b1.y);
        }
    }
    __syncthreads();

    // ---- cross-stream reduction into stream 0 ----
    u64* red = (u64*)sraw;                 // reuse stream-0 tile space (24 KB)
    if (s > 0) {
        u64* dst = red + (size_t)(s - 1) * 128 * 8 + r * 8;
#pragma unroll
        for (int i = 0; i < 2; i++)
#pragma unroll
            for (int j = 0; j < 4; j++) dst[i * 4 + j] = acc[i][j];
    }
    __syncthreads();
    if (s == 0) {
#pragma unroll
        for (int ss = 0; ss < 3; ss++) {
            const u64* src = red + (size_t)ss * 128 * 8 + r * 8;
#pragma unroll
            for (int i = 0; i < 2; i++)
#pragma unroll
                for (int j = 0; j < 4; j++) add2(acc[i][j], src[i * 4 + j]);
        }
    }
    // NOTE: caller always has a block-wide barrier (grid_sync) before the
    // next gemm4s call, which protects the red region from prologue writes.
}

// ============================================================
// Precompute: g_X?[(t*B+b)][j] = X[t,b,:] @ W_x?[:,j] + b_?[j]
// grid = (H_DIM/32, TB/64, 3). Bias added HERE ONLY.
// ============================================================
__global__ void __launch_bounds__(NT, 1)
xproj_kernel(const float* __restrict__ X,
             const float* __restrict__ Wz,
             const float* __restrict__ Wr,
             const float* __restrict__ Wh,
             const float* __restrict__ bz,
             const float* __restrict__ br,
             const float* __restrict__ bh)
{
    extern __shared__ char sraw[];
    const float* W;
    const float* bias;
    float* out;
    int g = blockIdx.z;
    if (g == 0)      { W = Wz; bias = bz; out = g_XZ; }
    else if (g == 1) { W = Wr; bias = br; out = g_XR; }
    else             { W = Wh; bias = bh; out = g_XH; }

    const int n0 = blockIdx.x * 32;
    const int m0 = blockIdx.y * 64;
    const int tid = threadIdx.x;

    u64 acc[2][4];
    gemm4s(X + (size_t)m0 * I_DIM, W, I_DIM, H_DIM, n0, tid, sraw, acc);

    if ((tid >> 7) == 0) {
        const int r = tid & 127;
        const int tx = r & 7;
        const int ty = r >> 3;
#pragma unroll
        for (int rp = 0; rp < 2; ++rp)
#pragma unroll
            for (int cc = 0; cc < 4; ++cc) {
                float2 v = unpack2(acc[rp][cc]);
                int mrow = m0 + ty * 4 + rp * 2;
                int c = n0 + tx * 4 + cc;
                float bb = bias[c];
                out[(size_t)mrow * H_DIM + c] = v.x + bb;
                out[(size_t)(mrow + 1) * H_DIM + c] = v.y + bb;
            }
    }
}

// ============================================================
// Grid-wide barrier (monotonic counter; host resets per launch).
// ============================================================
__device__ __forceinline__ void grid_sync(unsigned target)
{
    __syncthreads();
    if (threadIdx.x == 0) {
        __threadfence();
        atomicAdd(&g_bar_cnt, 1u);
        unsigned v;
        for (;;) {
            asm volatile("ld.global.acquire.gpu.u32 %0, [%1];"
                         : "=r"(v) : "l"(&g_bar_cnt));
            if (v >= target) break;
            __nanosleep(64);
        }
    }
    __syncthreads();
}

// ============================================================
// Persistent recurrence. Per step:
//  P1 (blk 0..127): Z = sig(XZ + H@Whz); RH = sig(XR + H@Whr) * H
//  barrier
//  P2 (blk 0..63):  Hnew = Z*H + (1-Z)*tanh(XH + RH@Whh)
//     (blk 64..95): Y[t-1] = H@Whq + b_hq
//  barrier
// ============================================================
__global__ void __launch_bounds__(NT, 1)
gru_persistent(const float* __restrict__ Whz,
               const float* __restrict__ Whr,
               const float* __restrict__ Whh,
               const float* __restrict__ Whq,
               const float* __restrict__ bq,
               float* __restrict__ out,
               int write_hfinal)
{
    extern __shared__ char sraw[];
    const int blk = blockIdx.x;
    const int tid = threadIdx.x;
    const int r = tid & 127;
    const int tx = r & 7;
    const int ty = r >> 3;
    const bool epi = (tid >> 7) == 0;
    unsigned epoch = 0;
    u64 acc[2][4];

    for (int t = 0; t < T_DIM; ++t) {
        const float* Hold = g_H[t & 1];
        float* Hnew = g_H[(t + 1) & 1];

        // ---------------- P1: gates Z, R ----------------
        if (blk < 128) {
            const int gate = blk >> 6;
            const int n0 = (blk & 63) * 32;
            const float* W  = gate ? Whr  : Whz;
            const float* Xp = gate ? g_XR : g_XZ;

            gemm4s(Hold, W, H_DIM, H_DIM, n0, tid, sraw, acc);

            if (epi) {
#pragma unroll
                for (int rp = 0; rp < 2; ++rp)
#pragma unroll
                    for (int cc = 0; cc < 4; ++cc) {
                        float2 v = unpack2(acc[rp][cc]);
                        int b = ty * 4 + rp * 2;
                        int c = n0 + tx * 4 + cc;
#pragma unroll
                        for (int rr = 0; rr < 2; ++rr) {
                            float vv = rr ? v.y : v.x;
                            float x = Xp[(size_t)(t * B_DIM + b + rr) * H_DIM + c] + vv;
                            float sg = 1.0f / (1.0f + expf(-x));
                            if (gate) g_RH[(b + rr) * H_DIM + c] = sg * Hold[(b + rr) * H_DIM + c];
                            else      g_Z[(b + rr) * H_DIM + c]  = sg;
                        }
                    }
            }
        }
        epoch++; grid_sync(epoch * NB);

        // ---------------- P2: Hnew and Y[t-1] ----------------
        if (blk < 64) {
            const int n0 = blk * 32;
            gemm4s(g_RH, Whh, H_DIM, H_DIM, n0, tid, sraw, acc);

            if (epi) {
#pragma unroll
                for (int rp = 0; rp < 2; ++rp)
#pragma unroll
                    for (int cc = 0; cc < 4; ++cc) {
                        float2 v = unpack2(acc[rp][cc]);
                        int b = ty * 4 + rp * 2;
                        int c = n0 + tx * 4 + cc;
#pragma unroll
                        for (int rr = 0; rr < 2; ++rr) {
                            float vv = rr ? v.y : v.x;
                            float ht = tanhf(g_XH[(size_t)(t * B_DIM + b + rr) * H_DIM + c] + vv);
                            float z = g_Z[(b + rr) * H_DIM + c];
                            Hnew[(b + rr) * H_DIM + c] =
                                z * Hold[(b + rr) * H_DIM + c] + (1.0f - z) * ht;
                        }
                    }
            }
        } else if (blk < 96 && t > 0) {
            const int n0 = (blk - 64) * 32;
            gemm4s(Hold, Whq, H_DIM, I_DIM, n0, tid, sraw, acc);

            if (epi) {
#pragma unroll
                for (int rp = 0; rp < 2; ++rp)
#pragma unroll
                    for (int cc = 0; cc < 4; ++cc) {
                        float2 v = unpack2(acc[rp][cc]);
                        int b = ty * 4 + rp * 2;
                        int c = n0 + tx * 4 + cc;
                        float bb = bq[c];
                        out[(size_t)((t - 1) * B_DIM + b) * I_DIM + c] = v.x + bb;
                        out[(size_t)((t - 1) * B_DIM + b + 1) * I_DIM + c] = v.y + bb;
                    }
            }
        }
        epoch++; grid_sync(epoch * NB);
    }

    // ---------------- tail: Y[T-1] + optional H_final ----------------
    const float* Hfin = g_H[T_DIM & 1];   // T even -> g_H[0]
    if (blk < 32) {
        const int n0 = blk * 32;
        gemm4s(Hfin, Whq, H_DIM, I_DIM, n0, tid, sraw, acc);
        if (epi) {
#pragma unroll
            for (int rp = 0; rp < 2; ++rp)
#pragma unroll
                for (int cc = 0; cc < 4; ++cc) {
                    float2 v = unpack2(acc[rp][cc]);
                    int b = ty * 4 + rp * 2;
                    int c = n0 + tx * 4 + cc;
                    float bb = bq[c];
                    out[(size_t)((T_DIM - 1) * B_DIM + b) * I_DIM + c] = v.x + bb;
                    out[(size_t)((T_DIM - 1) * B_DIM + b + 1) * I_DIM + c] = v.y + bb;
                }
        }
    } else if (blk >= 32 && blk < 64 && write_hfinal) {
        float* dst = out + (size_t)TB * I_DIM;
        int base = ((blk - 32) * NT + tid) * 8;   // 32*512*8 = 131072
        *(float4*)&dst[base]     = *(const float4*)&Hfin[base];
        *(float4*)&dst[base + 4] = *(const float4*)&Hfin[base + 4];
    }
}

extern "C" void kernel_launch(void* const* d_in, const int* in_sizes, int n_in,
                              void* d_out, int out_size)
{
    (void)in_sizes; (void)n_in;
    const float* inputs = (const float*)d_in[0];
    const float* state  = (const float*)d_in[1];
    const float* W_xz   = (const float*)d_in[2];
    const float* W_hz   = (const float*)d_in[3];
    const float* b_z    = (const float*)d_in[4];
    const float* W_xr   = (const float*)d_in[5];
    const float* W_hr   = (const float*)d_in[6];
    const float* b_r    = (const float*)d_in[7];
    const float* W_xh   = (const float*)d_in[8];
    const float* W_hh   = (const float*)d_in[9];
    const float* b_h    = (const float*)d_in[10];
    const float* W_hq   = (const float*)d_in[11];
    const float* b_hq   = (const float*)d_in[12];
    float* out = (float*)d_out;

    static int attrs_set = 0;
    if (!attrs_set) {
        cudaFuncSetAttribute(xproj_kernel,
                             cudaFuncAttributeMaxDynamicSharedMemorySize, SMEM_BYTES);
        cudaFuncSetAttribute(gru_persistent,
                             cudaFuncAttributeMaxDynamicSharedMemorySize, SMEM_BYTES);
        attrs_set = 1;
    }

    float* hbuf = nullptr;
    cudaGetSymbolAddress((void**)&hbuf, g_H);
    unsigned* barp = nullptr;
    cudaGetSymbolAddress((void**)&barp, g_bar_cnt);

    cudaMemsetAsync(barp, 0, sizeof(unsigned), 0);
    cudaMemcpyAsync(hbuf, state, (size_t)B_DIM * H_DIM * sizeof(float),
                    cudaMemcpyDeviceToDevice, 0);

    dim3 gx(H_DIM / 32, TB / 64, 3);
    xproj_kernel<<<gx, NT, SMEM_BYTES>>>(inputs, W_xz, W_xr, W_xh, b_z, b_r, b_h);

    long long need = (long long)TB * I_DIM + (long long)B_DIM * H_DIM;
    int write_hfinal = ((long long)out_size >= need) ? 1 : 0;

    gru_persistent<<<NB, NT, SMEM_BYTES>>>(W_hz, W_hr, W_hh, W_hq, b_hq, out, write_hfinal);
}